// round 5
// baseline (speedup 1.0000x reference)
#include <cuda_runtime.h>
#include <cstddef>

#define BATCH   8
#define NPTS    8192
#define CFEAT   32
#define NPOINT  1024
#define NSAMPLE 32
#define OUTC    35            // 3 (centered xyz) + 32 (features)
#define R2      0.0625f       // 0.25^2, exact in fp32

typedef unsigned long long u64;

// Spatially sorted copies of xyz (per batch) + original indices.
__device__ float d_sx[BATCH * NPTS];
__device__ float d_sy[BATCH * NPTS];
__device__ float d_sz[BATCH * NPTS];
__device__ int   d_sorig[BATCH * NPTS];

// 4-bit Morton spread: bit k of input -> bit 3k of output.
__constant__ unsigned short MORT4[16] = {
    0, 1, 8, 9, 64, 65, 72, 73, 512, 513, 520, 521, 576, 577, 584, 585
};

// ---------------------------------------------------------------------------
__device__ __forceinline__ unsigned redux_max_u32(unsigned v) {
    unsigned r;
    asm volatile("redux.sync.max.u32 %0, %1, 0xffffffff;" : "=r"(r) : "r"(v));
    return r;
}
__device__ __forceinline__ int redux_min_s32(int v) {
    int r;
    asm volatile("redux.sync.min.s32 %0, %1, 0xffffffff;" : "=r"(r) : "r"(v));
    return r;
}

// Packed f32x2 helpers (Blackwell). Each half rounds with .rn — bit-identical
// to the scalar op on that half, so FPS distance math stays bit-exact.
__device__ __forceinline__ u64 pk2(float lo, float hi) {
    u64 r; asm("mov.b64 %0, {%1, %2};" : "=l"(r) : "f"(lo), "f"(hi)); return r;
}
__device__ __forceinline__ float2 upk2(u64 v) {
    float lo, hi; asm("mov.b64 {%0, %1}, %2;" : "=f"(lo), "=f"(hi) : "l"(v));
    return make_float2(lo, hi);
}
__device__ __forceinline__ u64 addx2(u64 a, u64 b) {
    u64 r; asm("add.rn.f32x2 %0, %1, %2;" : "=l"(r) : "l"(a), "l"(b)); return r;
}
__device__ __forceinline__ u64 mulx2(u64 a, u64 b) {
    u64 r; asm("mul.rn.f32x2 %0, %1, %2;" : "=l"(r) : "l"(a), "l"(b)); return r;
}

// ---------------------------------------------------------------------------
// Kernel 0: Morton-grid counting sort, one block per batch. Order within a
// cell is atomic-nondeterministic — harmless: prune-skips are exact no-ops,
// so the FPS trajectory is independent of the sorted order.
// ---------------------------------------------------------------------------
__global__ __launch_bounds__(1024, 1)
void sort_kernel(const float* __restrict__ xyz) {
    const int b = blockIdx.x;
    const int t = threadIdx.x;
    const float* X = xyz + (size_t)b * NPTS * 3;

    __shared__ unsigned hist[4096];
    __shared__ unsigned warpsum[32];

#pragma unroll
    for (int c = t; c < 4096; c += 1024) hist[c] = 0;
    __syncthreads();

    unsigned cell[8];
#pragma unroll
    for (int j = 0; j < 8; j++) {
        const int i = t + j * 1024;
        const float x = X[3 * i + 0];
        const float y = X[3 * i + 1];
        const float z = X[3 * i + 2];
        const int ix = (int)fminf(fmaxf((x + 5.0f) * 1.6f, 0.0f), 15.0f);
        const int iy = (int)fminf(fmaxf((y + 5.0f) * 1.6f, 0.0f), 15.0f);
        const int iz = (int)fminf(fmaxf((z + 5.0f) * 1.6f, 0.0f), 15.0f);
        cell[j] = (unsigned)MORT4[ix] | ((unsigned)MORT4[iy] << 1)
                | ((unsigned)MORT4[iz] << 2);
        atomicAdd(&hist[cell[j]], 1u);
    }
    __syncthreads();

    const unsigned h0 = hist[4 * t + 0];
    const unsigned h1 = hist[4 * t + 1];
    const unsigned h2 = hist[4 * t + 2];
    const unsigned h3 = hist[4 * t + 3];
    const unsigned local = h0 + h1 + h2 + h3;
    unsigned inc = local;
#pragma unroll
    for (int o = 1; o < 32; o <<= 1) {
        const unsigned v = __shfl_up_sync(0xffffffff, inc, o);
        if ((t & 31) >= o) inc += v;
    }
    if ((t & 31) == 31) warpsum[t >> 5] = inc;
    __syncthreads();
    if (t < 32) {
        const unsigned v = warpsum[t];
        unsigned i2 = v;
#pragma unroll
        for (int o = 1; o < 32; o <<= 1) {
            const unsigned u = __shfl_up_sync(0xffffffff, i2, o);
            if (t >= o) i2 += u;
        }
        warpsum[t] = i2 - v;   // exclusive
    }
    __syncthreads();
    const unsigned excl = warpsum[t >> 5] + inc - local;
    hist[4 * t + 0] = excl;
    hist[4 * t + 1] = excl + h0;
    hist[4 * t + 2] = excl + h0 + h1;
    hist[4 * t + 3] = excl + h0 + h1 + h2;
    __syncthreads();

    const int base = b * NPTS;
#pragma unroll
    for (int j = 0; j < 8; j++) {
        const int i = t + j * 1024;
        const unsigned pos = atomicAdd(&hist[cell[j]], 1u);
        d_sx[base + pos] = X[3 * i + 0];
        d_sy[base + pos] = X[3 * i + 1];
        d_sz[base + pos] = X[3 * i + 2];
        d_sorig[base + pos] = i;
    }
}

// ---------------------------------------------------------------------------
// Kernel 1: FPS, latency-chain-optimized.
// - Exact warp AABB pruning (skip == bit-exact no-op, >1000x fp margin).
// - Winner warp broadcasts its candidate's COORDS through smem (LDS 29cyc)
//   instead of every warp re-loading the center from global (cold L2 ~240cyc
//   on the serial chain — the round-3/4 bottleneck).
// - Original indices staged in smem; tie-scan is LDS, not cold LDG.
// - One barrier per iteration; parity double-buffered warp slots; per-warp
//   (key,idx,x,y,z) cached by an "owner lane" across pruned iterations.
// ---------------------------------------------------------------------------
__global__ __launch_bounds__(1024, 1)
void fps_kernel(const float* __restrict__ xyz, float* __restrict__ new_xyz) {
    const int b = blockIdx.x;
    const int t = threadIdx.x;
    const int lane = t & 31;
    const int w = t >> 5;
    const float* X = xyz + (size_t)b * NPTS * 3;
    float* O = new_xyz + (size_t)b * NPOINT * 3;
    const int tbase = b * NPTS + t * 8;

    __shared__ int      s_orig[NPTS];          // 32KB: orig idx, sorted order
    __shared__ unsigned s_wv[2][32];
    __shared__ int      s_wi[2][32];
    __shared__ float    s_cx[2][32], s_cy[2][32], s_cz[2][32];

    // Stage original indices (coalesced, one-time).
#pragma unroll
    for (int j = 0; j < 8; j++)
        s_orig[t + j * 1024] = d_sorig[b * NPTS + t + j * 1024];

    // Packed coords: pair q = sorted points t*8+2q (lo), t*8+2q+1 (hi).
    u64 pxp[4], pyp[4], pzp[4];
    float dist[8];
    float alx = 1e38f, aly = 1e38f, alz = 1e38f;
    float ahx = -1e38f, ahy = -1e38f, ahz = -1e38f;
#pragma unroll
    for (int q = 0; q < 4; q++) {
        pxp[q] = ((const u64*)(d_sx + tbase))[q];
        pyp[q] = ((const u64*)(d_sy + tbase))[q];
        pzp[q] = ((const u64*)(d_sz + tbase))[q];
        const float2 xx = upk2(pxp[q]);
        const float2 yy = upk2(pyp[q]);
        const float2 zz = upk2(pzp[q]);
        alx = fminf(alx, fminf(xx.x, xx.y)); ahx = fmaxf(ahx, fmaxf(xx.x, xx.y));
        aly = fminf(aly, fminf(yy.x, yy.y)); ahy = fmaxf(ahy, fmaxf(yy.x, yy.y));
        alz = fminf(alz, fminf(zz.x, zz.y)); ahz = fmaxf(ahz, fmaxf(zz.x, zz.y));
        dist[2 * q] = 1e38f; dist[2 * q + 1] = 1e38f;
    }
#pragma unroll
    for (int o = 16; o > 0; o >>= 1) {
        alx = fminf(alx, __shfl_xor_sync(0xffffffff, alx, o));
        aly = fminf(aly, __shfl_xor_sync(0xffffffff, aly, o));
        alz = fminf(alz, __shfl_xor_sync(0xffffffff, alz, o));
        ahx = fmaxf(ahx, __shfl_xor_sync(0xffffffff, ahx, o));
        ahy = fmaxf(ahy, __shfl_xor_sync(0xffffffff, ahy, o));
        ahz = fmaxf(ahz, __shfl_xor_sync(0xffffffff, ahz, o));
    }
    __syncthreads();   // s_orig visible

    float lx = X[0], ly = X[1], lz = X[2];   // first center = point 0
    if (t == 0) { O[0] = lx; O[1] = ly; O[2] = lz; }

    unsigned wbest = 0x7f7fffffu;   // FLT_MAX bits: forces update in iter 1
    int   wbidx = 0;
    bool  c_own = false;            // this lane owns the warp's cached best
    float c_x = 0.f, c_y = 0.f, c_z = 0.f;

    for (int k = 1; k < NPOINT; k++) {
        const int buf = k & 1;
        // Conservative lower bound on d2 from center to warp AABB.
        const float bx = fmaxf(fmaxf(alx - lx, lx - ahx), 0.0f);
        const float by = fmaxf(fmaxf(aly - ly, ly - ahy), 0.0f);
        const float bz = fmaxf(fmaxf(alz - lz, lz - ahz), 0.0f);
        const float L = bx * bx + by * by + bz * bz;

        if (L * 0.999f < __uint_as_float(wbest)) {   // warp-uniform
            const unsigned nbx = __float_as_uint(lx) ^ 0x80000000u;
            const unsigned nby = __float_as_uint(ly) ^ 0x80000000u;
            const unsigned nbz = __float_as_uint(lz) ^ 0x80000000u;
            const u64 nlx2 = pk2(__uint_as_float(nbx), __uint_as_float(nbx));
            const u64 nly2 = pk2(__uint_as_float(nby), __uint_as_float(nby));
            const u64 nlz2 = pk2(__uint_as_float(nbz), __uint_as_float(nbz));
#pragma unroll
            for (int q = 0; q < 4; q++) {
                const u64 dx = addx2(pxp[q], nlx2);
                const u64 dy = addx2(pyp[q], nly2);
                const u64 dz = addx2(pzp[q], nlz2);
                // ((dx^2 + dy^2) + dz^2) — same association as reference.
                const u64 s = addx2(addx2(mulx2(dx, dx), mulx2(dy, dy)),
                                    mulx2(dz, dz));
                const float2 d2 = upk2(s);
                dist[2 * q]     = fminf(dist[2 * q],     d2.x);
                dist[2 * q + 1] = fminf(dist[2 * q + 1], d2.y);
            }
            const float best = fmaxf(
                fmaxf(fmaxf(dist[0], dist[1]), fmaxf(dist[2], dist[3])),
                fmaxf(fmaxf(dist[4], dist[5]), fmaxf(dist[6], dist[7])));

            // Warp argmax; ties -> min ORIGINAL index (jnp.argmax semantics).
            const unsigned vb = __float_as_uint(best);
            const unsigned wmax = redux_max_u32(vb);
            int cand = 0x7fffffff;
            int jb = -1;
            if (vb == wmax) {
#pragma unroll
                for (int j = 0; j < 8; j++) {
                    if (__float_as_uint(dist[j]) == wmax) {
                        const int o = s_orig[t * 8 + j];
                        if (o < cand) { cand = o; jb = j; }
                    }
                }
            }
            wbidx = redux_min_s32(cand);
            wbest = wmax;
            c_own = (cand == wbidx) && (cand != 0x7fffffff);
            if (c_own) {
#pragma unroll
                for (int j = 0; j < 8; j++) {
                    if (j == jb) {
                        const float2 xx = upk2(pxp[j >> 1]);
                        const float2 yy = upk2(pyp[j >> 1]);
                        const float2 zz = upk2(pzp[j >> 1]);
                        c_x = (j & 1) ? xx.y : xx.x;
                        c_y = (j & 1) ? yy.y : yy.x;
                        c_z = (j & 1) ? zz.y : zz.x;
                    }
                }
            }
        }
        // Owner lane publishes this warp's (key, idx, coords) for this parity.
        if (c_own) {
            s_wv[buf][w] = wbest;  s_wi[buf][w] = wbidx;
            s_cx[buf][w] = c_x;    s_cy[buf][w] = c_y;   s_cz[buf][w] = c_z;
        }
        __syncthreads();

        // Every warp reduces all 32 warp keys itself (no 2nd barrier).
        const unsigned v2 = s_wv[buf][lane];
        const int      i2 = s_wi[buf][lane];
        const unsigned m2 = redux_max_u32(v2);
        const int c2 = (v2 == m2) ? i2 : 0x7fffffff;
        const int wi = redux_min_s32(c2);
        // Winner warp slot (any slot with the same orig idx holds identical
        // coords bits, so __ffs choice is unambiguous).
        const unsigned bm = __ballot_sync(0xffffffff, (v2 == m2) && (i2 == wi));
        const int wl = __ffs(bm) - 1;

        lx = s_cx[buf][wl];
        ly = s_cy[buf][wl];
        lz = s_cz[buf][wl];
        if (t == 0) { O[3 * k] = lx; O[3 * k + 1] = ly; O[3 * k + 2] = lz; }
    }
}

// ---------------------------------------------------------------------------
// Kernel 2: fused ball query + grouping. One warp per center. The in-radius
// scan is batched 8 ballots (256 points) per early-exit check: the 24 loads
// and 8 distance computations per super-chunk are independent (deep MLP);
// the serialized cnt/ballot chain is 8x shorter than the per-32 version.
// ---------------------------------------------------------------------------
__global__ __launch_bounds__(256)
void ballgroup_kernel(const float* __restrict__ xyz,
                      const float* __restrict__ points,
                      const float* __restrict__ new_xyz,
                      float* __restrict__ new_points) {
    const int gwarp = (blockIdx.x * blockDim.x + threadIdx.x) >> 5;
    const int lane  = threadIdx.x & 31;
    const int wslot = threadIdx.x >> 5;
    if (gwarp >= BATCH * NPOINT) return;

    const int b = gwarp / NPOINT;
    const int p = gwarp % NPOINT;

    const float* X   = xyz    + (size_t)b * NPTS * 3;
    const float* P   = points + (size_t)b * NPTS * CFEAT;
    const float* ctr = new_xyz + (size_t)(b * NPOINT + p) * 3;
    const float cx = ctr[0], cy = ctr[1], cz = ctr[2];

    __shared__ int sidx[8][NSAMPLE];

    const unsigned lmask = (1u << lane) - 1u;
    int cnt = 0;
    for (int sb = 0; sb < NPTS && cnt < NSAMPLE; sb += 256) {
        unsigned m[8];
#pragma unroll
        for (int c = 0; c < 8; c++) {
            const int i = sb + c * 32 + lane;
            const float dx = X[3 * i + 0] - cx;
            const float dy = X[3 * i + 1] - cy;
            const float dz = X[3 * i + 2] - cz;
            const float d2 = __fadd_rn(__fadd_rn(__fmul_rn(dx, dx),
                                                 __fmul_rn(dy, dy)),
                                       __fmul_rn(dz, dz));
            m[c] = __ballot_sync(0xffffffff, d2 < R2);
        }
#pragma unroll
        for (int c = 0; c < 8; c++) {
            const int i = sb + c * 32 + lane;
            const bool in = (m[c] >> lane) & 1u;
            const int pos = cnt + __popc(m[c] & lmask);
            if (in && pos < NSAMPLE) sidx[wslot][pos] = i;
            cnt += __popc(m[c]);
        }
    }
    __syncwarp();

    const int nvalid = cnt < NSAMPLE ? cnt : NSAMPLE;
    const int first  = sidx[wslot][0];
    const int myidx  = (lane < nvalid) ? sidx[wslot][lane] : first;
    sidx[wslot][lane] = myidx;
    __syncwarp();

    float* OUT = new_points + (size_t)(b * NPOINT + p) * NSAMPLE * OUTC;
    const float cc = (lane == 0) ? cx : ((lane == 1) ? cy : cz);

#pragma unroll
    for (int s0 = 0; s0 < NSAMPLE; s0 += 4) {
        int id[4];
#pragma unroll
        for (int u = 0; u < 4; u++) id[u] = sidx[wslot][s0 + u];
#pragma unroll
        for (int u = 0; u < 4; u++) {
            const int idx = id[u];
            float v;
            if (lane < 3) {
                v = X[3 * idx + lane] - cc;
            } else {
                v = P[(size_t)idx * CFEAT + (lane - 3)];
            }
            OUT[(s0 + u) * OUTC + lane] = v;
            if (lane < 3) {
                OUT[(s0 + u) * OUTC + 32 + lane] =
                    P[(size_t)idx * CFEAT + 29 + lane];
            }
        }
    }
}

// ---------------------------------------------------------------------------
extern "C" void kernel_launch(void* const* d_in, const int* in_sizes, int n_in,
                              void* d_out, int out_size) {
    const float* xyz    = (const float*)d_in[0];
    const float* points = (const float*)d_in[1];
    float* new_xyz    = (float*)d_out;
    float* new_points = new_xyz + (size_t)BATCH * NPOINT * 3;

    sort_kernel<<<BATCH, 1024>>>(xyz);
    fps_kernel<<<BATCH, 1024>>>(xyz, new_xyz);

    const int nwarps  = BATCH * NPOINT;
    const int threads = 256;
    const int blocks  = (nwarps * 32) / threads;
    ballgroup_kernel<<<blocks, threads>>>(xyz, points, new_xyz, new_points);
}

// round 6
// speedup vs baseline: 1.2730x; 1.2730x over previous
#include <cuda_runtime.h>
#include <cstddef>

#define BATCH   8
#define NPTS    8192
#define CFEAT   32
#define NPOINT  1024
#define NSAMPLE 32
#define OUTC    35            // 3 (centered xyz) + 32 (features)
#define R2      0.0625f       // 0.25^2, exact in fp32

typedef unsigned long long u64;

// Spatially sorted copies of xyz (per batch) + original indices.
__device__ float d_sx[BATCH * NPTS];
__device__ float d_sy[BATCH * NPTS];
__device__ float d_sz[BATCH * NPTS];
__device__ int   d_sorig[BATCH * NPTS];

// 4-bit Morton spread: bit k of input -> bit 3k of output.
__constant__ unsigned short MORT4[16] = {
    0, 1, 8, 9, 64, 65, 72, 73, 512, 513, 520, 521, 576, 577, 584, 585
};

// ---------------------------------------------------------------------------
__device__ __forceinline__ unsigned redux_max_u32(unsigned v) {
    unsigned r;
    asm volatile("redux.sync.max.u32 %0, %1, 0xffffffff;" : "=r"(r) : "r"(v));
    return r;
}
__device__ __forceinline__ int redux_min_s32(int v) {
    int r;
    asm volatile("redux.sync.min.s32 %0, %1, 0xffffffff;" : "=r"(r) : "r"(v));
    return r;
}

// Packed f32x2 helpers (Blackwell). Each half rounds with .rn — bit-identical
// to the scalar op on that half, so FPS distance math stays bit-exact.
__device__ __forceinline__ u64 pk2(float lo, float hi) {
    u64 r; asm("mov.b64 %0, {%1, %2};" : "=l"(r) : "f"(lo), "f"(hi)); return r;
}
__device__ __forceinline__ float2 upk2(u64 v) {
    float lo, hi; asm("mov.b64 {%0, %1}, %2;" : "=f"(lo), "=f"(hi) : "l"(v));
    return make_float2(lo, hi);
}
__device__ __forceinline__ u64 addx2(u64 a, u64 b) {
    u64 r; asm("add.rn.f32x2 %0, %1, %2;" : "=l"(r) : "l"(a), "l"(b)); return r;
}
__device__ __forceinline__ u64 mulx2(u64 a, u64 b) {
    u64 r; asm("mul.rn.f32x2 %0, %1, %2;" : "=l"(r) : "l"(a), "l"(b)); return r;
}

// ---------------------------------------------------------------------------
// Kernel 0: Morton-grid counting sort, one block per batch. Order within a
// cell is atomic-nondeterministic — harmless: prune-skips are exact no-ops,
// so the FPS trajectory is independent of the sorted order.
// ---------------------------------------------------------------------------
__global__ __launch_bounds__(1024, 1)
void sort_kernel(const float* __restrict__ xyz) {
    const int b = blockIdx.x;
    const int t = threadIdx.x;
    const float* X = xyz + (size_t)b * NPTS * 3;

    __shared__ unsigned hist[4096];
    __shared__ unsigned warpsum[32];

#pragma unroll
    for (int c = t; c < 4096; c += 1024) hist[c] = 0;
    __syncthreads();

    unsigned cell[8];
#pragma unroll
    for (int j = 0; j < 8; j++) {
        const int i = t + j * 1024;
        const float x = X[3 * i + 0];
        const float y = X[3 * i + 1];
        const float z = X[3 * i + 2];
        const int ix = (int)fminf(fmaxf((x + 5.0f) * 1.6f, 0.0f), 15.0f);
        const int iy = (int)fminf(fmaxf((y + 5.0f) * 1.6f, 0.0f), 15.0f);
        const int iz = (int)fminf(fmaxf((z + 5.0f) * 1.6f, 0.0f), 15.0f);
        cell[j] = (unsigned)MORT4[ix] | ((unsigned)MORT4[iy] << 1)
                | ((unsigned)MORT4[iz] << 2);
        atomicAdd(&hist[cell[j]], 1u);
    }
    __syncthreads();

    const unsigned h0 = hist[4 * t + 0];
    const unsigned h1 = hist[4 * t + 1];
    const unsigned h2 = hist[4 * t + 2];
    const unsigned h3 = hist[4 * t + 3];
    const unsigned local = h0 + h1 + h2 + h3;
    unsigned inc = local;
#pragma unroll
    for (int o = 1; o < 32; o <<= 1) {
        const unsigned v = __shfl_up_sync(0xffffffff, inc, o);
        if ((t & 31) >= o) inc += v;
    }
    if ((t & 31) == 31) warpsum[t >> 5] = inc;
    __syncthreads();
    if (t < 32) {
        const unsigned v = warpsum[t];
        unsigned i2 = v;
#pragma unroll
        for (int o = 1; o < 32; o <<= 1) {
            const unsigned u = __shfl_up_sync(0xffffffff, i2, o);
            if (t >= o) i2 += u;
        }
        warpsum[t] = i2 - v;   // exclusive
    }
    __syncthreads();
    const unsigned excl = warpsum[t >> 5] + inc - local;
    hist[4 * t + 0] = excl;
    hist[4 * t + 1] = excl + h0;
    hist[4 * t + 2] = excl + h0 + h1;
    hist[4 * t + 3] = excl + h0 + h1 + h2;
    __syncthreads();

    const int base = b * NPTS;
#pragma unroll
    for (int j = 0; j < 8; j++) {
        const int i = t + j * 1024;
        const unsigned pos = atomicAdd(&hist[cell[j]], 1u);
        d_sx[base + pos] = X[3 * i + 0];
        d_sy[base + pos] = X[3 * i + 1];
        d_sz[base + pos] = X[3 * i + 2];
        d_sorig[base + pos] = i;
    }
}

// ---------------------------------------------------------------------------
// Kernel 1: FPS, chain-optimized + register-slim.
// - Exact warp AABB pruning (skip == bit-exact no-op, >1000x fp margin).
// - Per-warp result (key, orig idx, sorted idx) is WARP-UNIFORM after the
//   reduction, so lane 0 republishes it every iteration into parity-double-
//   buffered smem slots — no owner-lane caching, no extra registers.
// - Next center's coords come from d_sx/d_sy/d_sz[sorted idx]: those arrays
//   are streamed at init and stay L1-resident (~39cyc hit) — replacing the
//   ~240cyc cold-L2 fetch that dominated the serial chain in rounds 2-4.
// - One barrier per iteration; every warp redundantly reduces the 32 keys.
// ---------------------------------------------------------------------------
__global__ __launch_bounds__(1024, 1)
void fps_kernel(const float* __restrict__ xyz, float* __restrict__ new_xyz) {
    const int b = blockIdx.x;
    const int t = threadIdx.x;
    const int lane = t & 31;
    const int w = t >> 5;
    float* O = new_xyz + (size_t)b * NPOINT * 3;
    const int bbase = b * NPTS;
    const int tbase = bbase + t * 8;

    // Packed coords: pair q = sorted points t*8+2q (lo), t*8+2q+1 (hi).
    u64 pxp[4], pyp[4], pzp[4];
    float dist[8];
    float alx = 1e38f, aly = 1e38f, alz = 1e38f;
    float ahx = -1e38f, ahy = -1e38f, ahz = -1e38f;
#pragma unroll
    for (int q = 0; q < 4; q++) {
        pxp[q] = ((const u64*)(d_sx + tbase))[q];
        pyp[q] = ((const u64*)(d_sy + tbase))[q];
        pzp[q] = ((const u64*)(d_sz + tbase))[q];
        const float2 xx = upk2(pxp[q]);
        const float2 yy = upk2(pyp[q]);
        const float2 zz = upk2(pzp[q]);
        alx = fminf(alx, fminf(xx.x, xx.y)); ahx = fmaxf(ahx, fmaxf(xx.x, xx.y));
        aly = fminf(aly, fminf(yy.x, yy.y)); ahy = fmaxf(ahy, fmaxf(yy.x, yy.y));
        alz = fminf(alz, fminf(zz.x, zz.y)); ahz = fmaxf(ahz, fmaxf(zz.x, zz.y));
        dist[2 * q] = 1e38f; dist[2 * q + 1] = 1e38f;
    }
#pragma unroll
    for (int o = 16; o > 0; o >>= 1) {
        alx = fminf(alx, __shfl_xor_sync(0xffffffff, alx, o));
        aly = fminf(aly, __shfl_xor_sync(0xffffffff, aly, o));
        alz = fminf(alz, __shfl_xor_sync(0xffffffff, alz, o));
        ahx = fmaxf(ahx, __shfl_xor_sync(0xffffffff, ahx, o));
        ahy = fmaxf(ahy, __shfl_xor_sync(0xffffffff, ahy, o));
        ahz = fmaxf(ahz, __shfl_xor_sync(0xffffffff, ahz, o));
    }

    __shared__ unsigned s_wv[2][32];   // warp best key (dist bits)
    __shared__ int      s_wi[2][32];   // warp best ORIGINAL idx
    __shared__ int      s_ws[2][32];   // warp best SORTED idx

    // First center = original point 0 (one cold load, off the steady chain).
    const float* X = xyz + (size_t)b * NPTS * 3;
    float lx = X[0], ly = X[1], lz = X[2];
    if (t == 0) { O[0] = lx; O[1] = ly; O[2] = lz; }

    unsigned wbest = 0x7f7fffffu;   // FLT_MAX bits: forces update in iter 1
    int wbidx = 0;                  // warp best original idx (uniform)
    int wbsrt = 0;                  // warp best sorted idx   (uniform)

    for (int k = 1; k < NPOINT; k++) {
        const int buf = k & 1;
        // Conservative lower bound on d2 from center to warp AABB.
        const float bx = fmaxf(fmaxf(alx - lx, lx - ahx), 0.0f);
        const float by = fmaxf(fmaxf(aly - ly, ly - ahy), 0.0f);
        const float bz = fmaxf(fmaxf(alz - lz, lz - ahz), 0.0f);
        const float L = bx * bx + by * by + bz * bz;

        if (L * 0.999f < __uint_as_float(wbest)) {   // warp-uniform branch
            const unsigned nbx = __float_as_uint(lx) ^ 0x80000000u;
            const unsigned nby = __float_as_uint(ly) ^ 0x80000000u;
            const unsigned nbz = __float_as_uint(lz) ^ 0x80000000u;
            const u64 nlx2 = pk2(__uint_as_float(nbx), __uint_as_float(nbx));
            const u64 nly2 = pk2(__uint_as_float(nby), __uint_as_float(nby));
            const u64 nlz2 = pk2(__uint_as_float(nbz), __uint_as_float(nbz));
#pragma unroll
            for (int q = 0; q < 4; q++) {
                const u64 dx = addx2(pxp[q], nlx2);
                const u64 dy = addx2(pyp[q], nly2);
                const u64 dz = addx2(pzp[q], nlz2);
                // ((dx^2 + dy^2) + dz^2) — same association as reference.
                const u64 s = addx2(addx2(mulx2(dx, dx), mulx2(dy, dy)),
                                    mulx2(dz, dz));
                const float2 d2 = upk2(s);
                dist[2 * q]     = fminf(dist[2 * q],     d2.x);
                dist[2 * q + 1] = fminf(dist[2 * q + 1], d2.y);
            }
            const float best = fmaxf(
                fmaxf(fmaxf(dist[0], dist[1]), fmaxf(dist[2], dist[3])),
                fmaxf(fmaxf(dist[4], dist[5]), fmaxf(dist[6], dist[7])));

            // Warp argmax; ties -> min ORIGINAL index (jnp.argmax semantics).
            const unsigned vb = __float_as_uint(best);
            const unsigned wmax = redux_max_u32(vb);
            int cand = 0x7fffffff;
            int jb = 0;
            if (vb == wmax) {
#pragma unroll
                for (int j = 7; j >= 0; j--) {
                    if (__float_as_uint(dist[j]) == wmax) {
                        const int o = d_sorig[tbase + j];   // L1-resident
                        if (o < cand) { cand = o; jb = j; }
                    }
                }
            }
            wbidx = redux_min_s32(cand);
            // Sorted idx of the winning lane's point (uniform via shfl).
            const unsigned bm = __ballot_sync(0xffffffff, cand == wbidx);
            wbsrt = __shfl_sync(0xffffffff, t * 8 + jb, __ffs(bm) - 1);
            wbest = wmax;
        }
        // Lane 0 republishes the (uniform) warp result every iteration.
        if (lane == 0) {
            s_wv[buf][w] = wbest; s_wi[buf][w] = wbidx; s_ws[buf][w] = wbsrt;
        }
        __syncthreads();

        // Every warp reduces all 32 warp keys itself (no 2nd barrier).
        const unsigned v2 = s_wv[buf][lane];
        const int      i2 = s_wi[buf][lane];
        const unsigned m2 = redux_max_u32(v2);
        const int c2 = (v2 == m2) ? i2 : 0x7fffffff;
        const int wi = redux_min_s32(c2);
        const unsigned bm2 = __ballot_sync(0xffffffff, (v2 == m2) && (i2 == wi));
        const int ws = s_ws[buf][__ffs(bm2) - 1];

        // Next center coords: L1-hit loads from the sorted copies.
        lx = d_sx[bbase + ws];
        ly = d_sy[bbase + ws];
        lz = d_sz[bbase + ws];
        if (t == 0) { O[3 * k] = lx; O[3 * k + 1] = ly; O[3 * k + 2] = lz; }
    }
}

// ---------------------------------------------------------------------------
// Kernel 2: fused ball query + grouping. One warp per center. The in-radius
// scan batches 8 ballots (256 points) per early-exit check: loads/math are
// independent (deep MLP); the serialized cnt/ballot chain is 8x shorter.
// ---------------------------------------------------------------------------
__global__ __launch_bounds__(256)
void ballgroup_kernel(const float* __restrict__ xyz,
                      const float* __restrict__ points,
                      const float* __restrict__ new_xyz,
                      float* __restrict__ new_points) {
    const int gwarp = (blockIdx.x * blockDim.x + threadIdx.x) >> 5;
    const int lane  = threadIdx.x & 31;
    const int wslot = threadIdx.x >> 5;
    if (gwarp >= BATCH * NPOINT) return;

    const int b = gwarp / NPOINT;
    const int p = gwarp % NPOINT;

    const float* X   = xyz    + (size_t)b * NPTS * 3;
    const float* P   = points + (size_t)b * NPTS * CFEAT;
    const float* ctr = new_xyz + (size_t)(b * NPOINT + p) * 3;
    const float cx = ctr[0], cy = ctr[1], cz = ctr[2];

    __shared__ int sidx[8][NSAMPLE];

    const unsigned lmask = (1u << lane) - 1u;
    int cnt = 0;
    for (int sb = 0; sb < NPTS && cnt < NSAMPLE; sb += 256) {
        unsigned m[8];
#pragma unroll
        for (int c = 0; c < 8; c++) {
            const int i = sb + c * 32 + lane;
            const float dx = X[3 * i + 0] - cx;
            const float dy = X[3 * i + 1] - cy;
            const float dz = X[3 * i + 2] - cz;
            const float d2 = __fadd_rn(__fadd_rn(__fmul_rn(dx, dx),
                                                 __fmul_rn(dy, dy)),
                                       __fmul_rn(dz, dz));
            m[c] = __ballot_sync(0xffffffff, d2 < R2);
        }
#pragma unroll
        for (int c = 0; c < 8; c++) {
            const int i = sb + c * 32 + lane;
            const bool in = (m[c] >> lane) & 1u;
            const int pos = cnt + __popc(m[c] & lmask);
            if (in && pos < NSAMPLE) sidx[wslot][pos] = i;
            cnt += __popc(m[c]);
        }
    }
    __syncwarp();

    const int nvalid = cnt < NSAMPLE ? cnt : NSAMPLE;
    const int first  = sidx[wslot][0];
    const int myidx  = (lane < nvalid) ? sidx[wslot][lane] : first;
    sidx[wslot][lane] = myidx;
    __syncwarp();

    float* OUT = new_points + (size_t)(b * NPOINT + p) * NSAMPLE * OUTC;
    const float cc = (lane == 0) ? cx : ((lane == 1) ? cy : cz);

#pragma unroll
    for (int s0 = 0; s0 < NSAMPLE; s0 += 4) {
        int id[4];
#pragma unroll
        for (int u = 0; u < 4; u++) id[u] = sidx[wslot][s0 + u];
#pragma unroll
        for (int u = 0; u < 4; u++) {
            const int idx = id[u];
            float v;
            if (lane < 3) {
                v = X[3 * idx + lane] - cc;
            } else {
                v = P[(size_t)idx * CFEAT + (lane - 3)];
            }
            OUT[(s0 + u) * OUTC + lane] = v;
            if (lane < 3) {
                OUT[(s0 + u) * OUTC + 32 + lane] =
                    P[(size_t)idx * CFEAT + 29 + lane];
            }
        }
    }
}

// ---------------------------------------------------------------------------
extern "C" void kernel_launch(void* const* d_in, const int* in_sizes, int n_in,
                              void* d_out, int out_size) {
    const float* xyz    = (const float*)d_in[0];
    const float* points = (const float*)d_in[1];
    float* new_xyz    = (float*)d_out;
    float* new_points = new_xyz + (size_t)BATCH * NPOINT * 3;

    sort_kernel<<<BATCH, 1024>>>(xyz);
    fps_kernel<<<BATCH, 1024>>>(xyz, new_xyz);

    const int nwarps  = BATCH * NPOINT;
    const int threads = 256;
    const int blocks  = (nwarps * 32) / threads;
    ballgroup_kernel<<<blocks, threads>>>(xyz, points, new_xyz, new_points);
}

// round 7
// speedup vs baseline: 1.3250x; 1.0409x over previous
#include <cuda_runtime.h>
#include <cstddef>

#define BATCH   8
#define NPTS    8192
#define CFEAT   32
#define NPOINT  1024
#define NSAMPLE 32
#define OUTC    35            // 3 (centered xyz) + 32 (features)
#define R2      0.0625f       // 0.25^2, exact in fp32

typedef unsigned long long u64;

// Spatially partitioned copies of xyz (per batch) + original indices.
__device__ float d_sx[BATCH * NPTS];
__device__ float d_sy[BATCH * NPTS];
__device__ float d_sz[BATCH * NPTS];
__device__ int   d_sorig[BATCH * NPTS];

// ---------------------------------------------------------------------------
__device__ __forceinline__ unsigned redux_max_u32(unsigned v) {
    unsigned r;
    asm volatile("redux.sync.max.u32 %0, %1, 0xffffffff;" : "=r"(r) : "r"(v));
    return r;
}
__device__ __forceinline__ int redux_min_s32(int v) {
    int r;
    asm volatile("redux.sync.min.s32 %0, %1, 0xffffffff;" : "=r"(r) : "r"(v));
    return r;
}

// Packed f32x2 helpers (Blackwell). Each half rounds with .rn — bit-identical
// to the scalar op on that half, so FPS distance math stays bit-exact.
__device__ __forceinline__ u64 pk2(float lo, float hi) {
    u64 r; asm("mov.b64 %0, {%1, %2};" : "=l"(r) : "f"(lo), "f"(hi)); return r;
}
__device__ __forceinline__ float2 upk2(u64 v) {
    float lo, hi; asm("mov.b64 {%0, %1}, %2;" : "=f"(lo), "=f"(hi) : "l"(v));
    return make_float2(lo, hi);
}
__device__ __forceinline__ u64 addx2(u64 a, u64 b) {
    u64 r; asm("add.rn.f32x2 %0, %1, %2;" : "=l"(r) : "l"(a), "l"(b)); return r;
}
__device__ __forceinline__ u64 mulx2(u64 a, u64 b) {
    u64 r; asm("mul.rn.f32x2 %0, %1, %2;" : "=l"(r) : "l"(a), "l"(b)); return r;
}

// ---------------------------------------------------------------------------
// Kernel 0: balanced spatial partition, one block per batch.
// 3-level quantile split: x -> 4 slabs (quartiles), y -> 4 per slab,
// z -> 2 per sub-slab. 32 EQUAL-COUNT (~256 pt) COMPACT boxes; warp w of the
// FPS kernel owns points [256w, 256w+256) — a compact box, unlike the
// equal-volume Morton grid (whose warp AABBs spanned ~3 units and killed
// pruning in rounds 3-6). Order within a group is atomic-nondeterministic —
// harmless: prune-skips are bit-exact no-ops, trajectory is order-invariant.
// ---------------------------------------------------------------------------
__global__ __launch_bounds__(1024, 1)
void partition_kernel(const float* __restrict__ xyz) {
    const int b = blockIdx.x;
    const int t = threadIdx.x;
    const float* X = xyz + (size_t)b * NPTS * 3;

    __shared__ int   hist[1024];
    __shared__ float bx[3];
    __shared__ float by[4][3];
    __shared__ float bz[16];
    __shared__ int   gbase[32];
    __shared__ int   gpos[32];

    float x[8], y[8], z[8];
#pragma unroll
    for (int j = 0; j < 8; j++) {
        const int i = t + j * 1024;
        x[j] = X[3 * i + 0]; y[j] = X[3 * i + 1]; z[j] = X[3 * i + 2];
    }

    // Robust defaults (if a boundary is never set, comparisons are false —
    // partition degrades to fewer groups but stays a valid permutation).
    if (t < 3)  bx[t] = 1e9f;
    if (t < 12) by[t >> 2][t & 3 > 2 ? 2 : (t & 3)] = 1e9f;  // see full init below
    if (t < 16) bz[t] = 1e9f;
    if (t < 12) by[t / 3][t % 3] = 1e9f;
    hist[t] = 0;
    __syncthreads();

    // ---- pass 1: x histogram, 256 bins over [-4,4] ----
    int bin[8];
#pragma unroll
    for (int j = 0; j < 8; j++) {
        bin[j] = min(max((int)((x[j] + 4.0f) * 32.0f), 0), 255);
        atomicAdd(&hist[bin[j]], 1);
    }
    __syncthreads();
    for (int off = 1; off < 256; off <<= 1) {       // inclusive scan [0,256)
        int v = 0;
        if (t < 256 && t >= off) v = hist[t - off];
        __syncthreads();
        if (t < 256) hist[t] += v;
        __syncthreads();
    }
    if (t < 256) {
        const int cum = hist[t];
        const int prev = t ? hist[t - 1] : 0;
#pragma unroll
        for (int q = 0; q < 3; q++) {
            const int T = (q + 1) * (NPTS / 4);
            if (prev < T && cum >= T) bx[q] = -4.0f + (t + 1) * (1.0f / 32.0f);
        }
    }
    __syncthreads();
    int slab[8];
#pragma unroll
    for (int j = 0; j < 8; j++)
        slab[j] = (x[j] > bx[0]) + (x[j] > bx[1]) + (x[j] > bx[2]);
    __syncthreads();

    // ---- pass 2: y histogram per slab, 4 x 256 bins ----
    hist[t] = 0;
    __syncthreads();
#pragma unroll
    for (int j = 0; j < 8; j++) {
        bin[j] = min(max((int)((y[j] + 4.0f) * 32.0f), 0), 255);
        atomicAdd(&hist[slab[j] * 256 + bin[j]], 1);
    }
    __syncthreads();
    for (int off = 1; off < 256; off <<= 1) {       // 4 parallel 256-scans
        int v = 0;
        if ((t & 255) >= off) v = hist[t - off];
        __syncthreads();
        hist[t] += v;
        __syncthreads();
    }
    {
        const int i = t & 255, s = t >> 8;
        const int cum = hist[t];
        const int prev = i ? hist[t - 1] : 0;
        const int tot = hist[s * 256 + 255];
#pragma unroll
        for (int q = 0; q < 3; q++) {
            const int T = (tot * (q + 1)) >> 2;
            if (T > 0 && prev < T && cum >= T)
                by[s][q] = -4.0f + (i + 1) * (1.0f / 32.0f);
        }
    }
    __syncthreads();
    int sub[8];
#pragma unroll
    for (int j = 0; j < 8; j++) {
        const int s = slab[j];
        sub[j] = s * 4 + (y[j] > by[s][0]) + (y[j] > by[s][1]) + (y[j] > by[s][2]);
    }
    __syncthreads();

    // ---- pass 3: z histogram per sub-slab, 16 x 64 bins ----
    hist[t] = 0;
    __syncthreads();
#pragma unroll
    for (int j = 0; j < 8; j++) {
        bin[j] = min(max((int)((z[j] + 4.0f) * 8.0f), 0), 63);
        atomicAdd(&hist[sub[j] * 64 + bin[j]], 1);
    }
    __syncthreads();
    for (int off = 1; off < 64; off <<= 1) {        // 16 parallel 64-scans
        int v = 0;
        if ((t & 63) >= off) v = hist[t - off];
        __syncthreads();
        hist[t] += v;
        __syncthreads();
    }
    {
        const int i = t & 63, s = t >> 6;
        const int cum = hist[t];
        const int prev = i ? hist[t - 1] : 0;
        const int tot = hist[s * 64 + 63];
        const int T = tot >> 1;
        if (T > 0 && prev < T && cum >= T) bz[s] = -4.0f + (i + 1) * 0.125f;
    }
    __syncthreads();
    int g[8];
#pragma unroll
    for (int j = 0; j < 8; j++) g[j] = sub[j] * 2 + (z[j] > bz[sub[j]]);
    __syncthreads();

    // ---- group counts -> bases -> scatter ----
    if (t < 32) hist[t] = 0;
    __syncthreads();
#pragma unroll
    for (int j = 0; j < 8; j++) atomicAdd(&hist[g[j]], 1);
    __syncthreads();
    if (t < 32) {
        const int v = hist[t];
        int e = v;
#pragma unroll
        for (int o = 1; o < 32; o <<= 1) {
            const int u2 = __shfl_up_sync(0xffffffff, e, o);
            if (t >= o) e += u2;
        }
        gbase[t] = e - v;    // exclusive
        gpos[t] = 0;
    }
    __syncthreads();
    const int bbase = b * NPTS;
#pragma unroll
    for (int j = 0; j < 8; j++) {
        const int i = t + j * 1024;
        const int p = gbase[g[j]] + atomicAdd(&gpos[g[j]], 1);
        d_sx[bbase + p] = x[j];
        d_sy[bbase + p] = y[j];
        d_sz[bbase + p] = z[j];
        d_sorig[bbase + p] = i;
    }
}

// ---------------------------------------------------------------------------
// Kernel 1: FPS with exact warp-AABB pruning (unchanged from round 6; the
// partition above is what makes the prune fire). Skip == bit-exact no-op.
// ---------------------------------------------------------------------------
__global__ __launch_bounds__(1024, 1)
void fps_kernel(const float* __restrict__ xyz, float* __restrict__ new_xyz) {
    const int b = blockIdx.x;
    const int t = threadIdx.x;
    const int lane = t & 31;
    const int w = t >> 5;
    float* O = new_xyz + (size_t)b * NPOINT * 3;
    const int bbase = b * NPTS;
    const int tbase = bbase + t * 8;

    u64 pxp[4], pyp[4], pzp[4];
    float dist[8];
    float alx = 1e38f, aly = 1e38f, alz = 1e38f;
    float ahx = -1e38f, ahy = -1e38f, ahz = -1e38f;
#pragma unroll
    for (int q = 0; q < 4; q++) {
        pxp[q] = ((const u64*)(d_sx + tbase))[q];
        pyp[q] = ((const u64*)(d_sy + tbase))[q];
        pzp[q] = ((const u64*)(d_sz + tbase))[q];
        const float2 xx = upk2(pxp[q]);
        const float2 yy = upk2(pyp[q]);
        const float2 zz = upk2(pzp[q]);
        alx = fminf(alx, fminf(xx.x, xx.y)); ahx = fmaxf(ahx, fmaxf(xx.x, xx.y));
        aly = fminf(aly, fminf(yy.x, yy.y)); ahy = fmaxf(ahy, fmaxf(yy.x, yy.y));
        alz = fminf(alz, fminf(zz.x, zz.y)); ahz = fmaxf(ahz, fmaxf(zz.x, zz.y));
        dist[2 * q] = 1e38f; dist[2 * q + 1] = 1e38f;
    }
#pragma unroll
    for (int o = 16; o > 0; o >>= 1) {
        alx = fminf(alx, __shfl_xor_sync(0xffffffff, alx, o));
        aly = fminf(aly, __shfl_xor_sync(0xffffffff, aly, o));
        alz = fminf(alz, __shfl_xor_sync(0xffffffff, alz, o));
        ahx = fmaxf(ahx, __shfl_xor_sync(0xffffffff, ahx, o));
        ahy = fmaxf(ahy, __shfl_xor_sync(0xffffffff, ahy, o));
        ahz = fmaxf(ahz, __shfl_xor_sync(0xffffffff, ahz, o));
    }

    __shared__ unsigned s_wv[2][32];   // warp best key (dist bits)
    __shared__ int      s_wi[2][32];   // warp best ORIGINAL idx
    __shared__ int      s_ws[2][32];   // warp best SORTED idx

    const float* X = xyz + (size_t)b * NPTS * 3;
    float lx = X[0], ly = X[1], lz = X[2];   // first center = point 0
    if (t == 0) { O[0] = lx; O[1] = ly; O[2] = lz; }

    unsigned wbest = 0x7f7fffffu;   // FLT_MAX bits: forces update in iter 1
    int wbidx = 0;
    int wbsrt = 0;

    for (int k = 1; k < NPOINT; k++) {
        const int buf = k & 1;
        const float bx = fmaxf(fmaxf(alx - lx, lx - ahx), 0.0f);
        const float by = fmaxf(fmaxf(aly - ly, ly - ahy), 0.0f);
        const float bz = fmaxf(fmaxf(alz - lz, lz - ahz), 0.0f);
        const float L = bx * bx + by * by + bz * bz;

        if (L * 0.999f < __uint_as_float(wbest)) {   // warp-uniform branch
            const unsigned nbx = __float_as_uint(lx) ^ 0x80000000u;
            const unsigned nby = __float_as_uint(ly) ^ 0x80000000u;
            const unsigned nbz = __float_as_uint(lz) ^ 0x80000000u;
            const u64 nlx2 = pk2(__uint_as_float(nbx), __uint_as_float(nbx));
            const u64 nly2 = pk2(__uint_as_float(nby), __uint_as_float(nby));
            const u64 nlz2 = pk2(__uint_as_float(nbz), __uint_as_float(nbz));
#pragma unroll
            for (int q = 0; q < 4; q++) {
                const u64 dx = addx2(pxp[q], nlx2);
                const u64 dy = addx2(pyp[q], nly2);
                const u64 dz = addx2(pzp[q], nlz2);
                // ((dx^2 + dy^2) + dz^2) — same association as reference.
                const u64 s = addx2(addx2(mulx2(dx, dx), mulx2(dy, dy)),
                                    mulx2(dz, dz));
                const float2 d2 = upk2(s);
                dist[2 * q]     = fminf(dist[2 * q],     d2.x);
                dist[2 * q + 1] = fminf(dist[2 * q + 1], d2.y);
            }
            const float best = fmaxf(
                fmaxf(fmaxf(dist[0], dist[1]), fmaxf(dist[2], dist[3])),
                fmaxf(fmaxf(dist[4], dist[5]), fmaxf(dist[6], dist[7])));

            // Warp argmax; ties -> min ORIGINAL index (jnp.argmax semantics).
            const unsigned vb = __float_as_uint(best);
            const unsigned wmax = redux_max_u32(vb);
            int cand = 0x7fffffff;
            int jb = 0;
            if (vb == wmax) {
#pragma unroll
                for (int j = 7; j >= 0; j--) {
                    if (__float_as_uint(dist[j]) == wmax) {
                        const int o = d_sorig[tbase + j];   // L1-resident
                        if (o < cand) { cand = o; jb = j; }
                    }
                }
            }
            wbidx = redux_min_s32(cand);
            const unsigned bm = __ballot_sync(0xffffffff, cand == wbidx);
            wbsrt = __shfl_sync(0xffffffff, t * 8 + jb, __ffs(bm) - 1);
            wbest = wmax;
        }
        if (lane == 0) {
            s_wv[buf][w] = wbest; s_wi[buf][w] = wbidx; s_ws[buf][w] = wbsrt;
        }
        __syncthreads();

        const unsigned v2 = s_wv[buf][lane];
        const int      i2 = s_wi[buf][lane];
        const unsigned m2 = redux_max_u32(v2);
        const int c2 = (v2 == m2) ? i2 : 0x7fffffff;
        const int wi = redux_min_s32(c2);
        const unsigned bm2 = __ballot_sync(0xffffffff, (v2 == m2) && (i2 == wi));
        const int ws = s_ws[buf][__ffs(bm2) - 1];

        lx = d_sx[bbase + ws];   // L1-hit loads from partitioned copies
        ly = d_sy[bbase + ws];
        lz = d_sz[bbase + ws];
        if (t == 0) { O[3 * k] = lx; O[3 * k + 1] = ly; O[3 * k + 2] = lz; }
    }
}

// ---------------------------------------------------------------------------
// Kernel 2: fused ball query + grouping (unchanged from round 6).
// ---------------------------------------------------------------------------
__global__ __launch_bounds__(256)
void ballgroup_kernel(const float* __restrict__ xyz,
                      const float* __restrict__ points,
                      const float* __restrict__ new_xyz,
                      float* __restrict__ new_points) {
    const int gwarp = (blockIdx.x * blockDim.x + threadIdx.x) >> 5;
    const int lane  = threadIdx.x & 31;
    const int wslot = threadIdx.x >> 5;
    if (gwarp >= BATCH * NPOINT) return;

    const int b = gwarp / NPOINT;
    const int p = gwarp % NPOINT;

    const float* X   = xyz    + (size_t)b * NPTS * 3;
    const float* P   = points + (size_t)b * NPTS * CFEAT;
    const float* ctr = new_xyz + (size_t)(b * NPOINT + p) * 3;
    const float cx = ctr[0], cy = ctr[1], cz = ctr[2];

    __shared__ int sidx[8][NSAMPLE];

    const unsigned lmask = (1u << lane) - 1u;
    int cnt = 0;
    for (int sb = 0; sb < NPTS && cnt < NSAMPLE; sb += 256) {
        unsigned m[8];
#pragma unroll
        for (int c = 0; c < 8; c++) {
            const int i = sb + c * 32 + lane;
            const float dx = X[3 * i + 0] - cx;
            const float dy = X[3 * i + 1] - cy;
            const float dz = X[3 * i + 2] - cz;
            const float d2 = __fadd_rn(__fadd_rn(__fmul_rn(dx, dx),
                                                 __fmul_rn(dy, dy)),
                                       __fmul_rn(dz, dz));
            m[c] = __ballot_sync(0xffffffff, d2 < R2);
        }
#pragma unroll
        for (int c = 0; c < 8; c++) {
            const int i = sb + c * 32 + lane;
            const bool in = (m[c] >> lane) & 1u;
            const int pos = cnt + __popc(m[c] & lmask);
            if (in && pos < NSAMPLE) sidx[wslot][pos] = i;
            cnt += __popc(m[c]);
        }
    }
    __syncwarp();

    const int nvalid = cnt < NSAMPLE ? cnt : NSAMPLE;
    const int first  = sidx[wslot][0];
    const int myidx  = (lane < nvalid) ? sidx[wslot][lane] : first;
    sidx[wslot][lane] = myidx;
    __syncwarp();

    float* OUT = new_points + (size_t)(b * NPOINT + p) * NSAMPLE * OUTC;
    const float cc = (lane == 0) ? cx : ((lane == 1) ? cy : cz);

#pragma unroll
    for (int s0 = 0; s0 < NSAMPLE; s0 += 4) {
        int id[4];
#pragma unroll
        for (int u = 0; u < 4; u++) id[u] = sidx[wslot][s0 + u];
#pragma unroll
        for (int u = 0; u < 4; u++) {
            const int idx = id[u];
            float v;
            if (lane < 3) {
                v = X[3 * idx + lane] - cc;
            } else {
                v = P[(size_t)idx * CFEAT + (lane - 3)];
            }
            OUT[(s0 + u) * OUTC + lane] = v;
            if (lane < 3) {
                OUT[(s0 + u) * OUTC + 32 + lane] =
                    P[(size_t)idx * CFEAT + 29 + lane];
            }
        }
    }
}

// ---------------------------------------------------------------------------
extern "C" void kernel_launch(void* const* d_in, const int* in_sizes, int n_in,
                              void* d_out, int out_size) {
    const float* xyz    = (const float*)d_in[0];
    const float* points = (const float*)d_in[1];
    float* new_xyz    = (float*)d_out;
    float* new_points = new_xyz + (size_t)BATCH * NPOINT * 3;

    partition_kernel<<<BATCH, 1024>>>(xyz);
    fps_kernel<<<BATCH, 1024>>>(xyz, new_xyz);

    const int nwarps  = BATCH * NPOINT;
    const int threads = 256;
    const int blocks  = (nwarps * 32) / threads;
    ballgroup_kernel<<<blocks, threads>>>(xyz, points, new_xyz, new_points);
}